// round 2
// baseline (speedup 1.0000x reference)
#include <cuda_runtime.h>

// out = clamp(floor(x * 16 + r) * (1/16), -8.0, 7.9375)
// WL=8, FL=4 -> sigma = 2^-4 (exact power of 2: mul by 16 / 0.0625 is exact).

__device__ __forceinline__ float quant1(float x, float r) {
    float q = floorf(fmaf(x, 16.0f, r)) * 0.0625f;
    q = fminf(q, 7.9375f);
    q = fmaxf(q, -8.0f);
    return q;
}

__device__ __forceinline__ float4 quant4(float4 xv, float4 rv) {
    float4 o;
    o.x = quant1(xv.x, rv.x);
    o.y = quant1(xv.y, rv.y);
    o.z = quant1(xv.z, rv.z);
    o.w = quant1(xv.w, rv.w);
    return o;
}

// Each thread handles float4 indices i and i + half: all 4 LDG.128s are
// independent and front-batched (MLP_p1 = 4), both halves stay coalesced.
__global__ void __launch_bounds__(256) quant_kernel_v4x2(
    const float4* __restrict__ x,
    const float4* __restrict__ r,
    float4* __restrict__ out,
    int half)
{
    int i = blockIdx.x * blockDim.x + threadIdx.x;
    if (i < half) {
        int j = i + half;
        float4 x0 = __ldcs(x + i);
        float4 r0 = __ldcs(r + i);
        float4 x1 = __ldcs(x + j);
        float4 r1 = __ldcs(r + j);
        __stcs(out + i, quant4(x0, r0));
        __stcs(out + j, quant4(x1, r1));
    }
}

__global__ void quant_kernel_tail(
    const float* __restrict__ x,
    const float* __restrict__ r,
    float* __restrict__ out,
    int start, int n)
{
    int i = start + blockIdx.x * blockDim.x + threadIdx.x;
    if (i < n) out[i] = quant1(x[i], r[i]);
}

extern "C" void kernel_launch(void* const* d_in, const int* in_sizes, int n_in,
                              void* d_out, int out_size) {
    const float* x = (const float*)d_in[0];
    const float* r = (const float*)d_in[1];
    float* out = (float*)d_out;
    int n = in_sizes[0];

    int n4 = n / 4;        // full float4 elements
    int half = n4 / 2;     // each thread does 2 float4s
    if (half > 0) {
        const int threads = 256;
        int blocks = (half + threads - 1) / threads;
        quant_kernel_v4x2<<<blocks, threads>>>(
            (const float4*)x, (const float4*)r, (float4*)out, half);
    }
    // Tail: anything not covered by the 2*half float4s (odd n4 or n % 4 != 0).
    int rem_start = half * 2 * 4;
    int rem = n - rem_start;
    if (rem > 0) {
        quant_kernel_tail<<<(rem + 255) / 256, 256>>>(x, r, out, rem_start, n);
    }
}

// round 3
// speedup vs baseline: 1.0110x; 1.0110x over previous
#include <cuda_runtime.h>

// out = clamp(floor(x * 16 + r) * (1/16), -8.0, 7.9375)
// WL=8, FL=4 -> sigma = 2^-4 (power of 2: *16 and *0.0625 are exact in fp32).
//
// Pure HBM-streaming kernel: 2 reads + 1 write of 512 MB each. Measured at
// ~89% of 8 TB/s spec; this revision minimizes per-thread overhead with one
// float4 per thread, exact grid, single linear coalesced stream (the best-
// measuring configuration; streaming hints / MLP batching measured neutral).

__device__ __forceinline__ float quant1(float x, float r) {
    float q = floorf(fmaf(x, 16.0f, r)) * 0.0625f;
    q = fminf(q, 7.9375f);
    q = fmaxf(q, -8.0f);
    return q;
}

__global__ void __launch_bounds__(256) quant_kernel_v4(
    const float4* __restrict__ x,
    const float4* __restrict__ r,
    float4* __restrict__ out,
    int n4)
{
    int i = blockIdx.x * blockDim.x + threadIdx.x;
    if (i < n4) {
        float4 xv = x[i];
        float4 rv = r[i];
        float4 o;
        o.x = quant1(xv.x, rv.x);
        o.y = quant1(xv.y, rv.y);
        o.z = quant1(xv.z, rv.z);
        o.w = quant1(xv.w, rv.w);
        out[i] = o;
    }
}

__global__ void quant_kernel_tail(
    const float* __restrict__ x,
    const float* __restrict__ r,
    float* __restrict__ out,
    int start, int n)
{
    int i = start + blockIdx.x * blockDim.x + threadIdx.x;
    if (i < n) out[i] = quant1(x[i], r[i]);
}

extern "C" void kernel_launch(void* const* d_in, const int* in_sizes, int n_in,
                              void* d_out, int out_size) {
    const float* x = (const float*)d_in[0];
    const float* r = (const float*)d_in[1];
    float* out = (float*)d_out;
    int n = in_sizes[0];

    int n4 = n / 4;
    if (n4 > 0) {
        const int threads = 256;
        int blocks = (n4 + threads - 1) / threads;  // exact: 131072 for n=2^27
        quant_kernel_v4<<<blocks, threads>>>(
            (const float4*)x, (const float4*)r, (float4*)out, n4);
    }
    int rem_start = n4 * 4;
    int rem = n - rem_start;
    if (rem > 0) {
        quant_kernel_tail<<<(rem + 255) / 256, 256>>>(x, r, out, rem_start, n);
    }
}